// round 15
// baseline (speedup 1.0000x reference)
#include <cuda_runtime.h>
#include <cuda_bf16.h>
#include <cuda_fp16.h>
#include <math.h>
#include <stdint.h>

#define MSZ   1024
#define M2    (MSZ * MSZ)
#define NPER  128
#define DDIM  64
#define NBAT  2048
#define NIDX  (NBAT * NPER)          // 262144
#define SIGN  (NBAT * NPER * DDIM)   // 16777216

// f32 scratch (6 x 4MB) + f16 planes (8 pairs hi/lo = 16 planes x 2MB)
__device__ float g_scratch[6 * M2];
__device__ __half g_hf[16 * M2];
__device__ int g_rows[NIDX];
__device__ unsigned int g_odd_or;

__device__ __forceinline__ uint32_t smem_u32(const void* p) {
    uint32_t a;
    asm("{ .reg .u64 t; cvta.to.shared.u64 t, %1; cvt.u32.u64 %0, t; }" : "=r"(a) : "l"(p));
    return a;
}
// f32x2 packed helpers
__device__ __forceinline__ unsigned long long pack2(float x, float y) {
    unsigned long long r;
    asm("mov.b64 %0, {%1, %2};" : "=l"(r) : "f"(x), "f"(y));
    return r;
}
__device__ __forceinline__ void fma2(unsigned long long& d,
                                     unsigned long long a, unsigned long long b) {
    asm("fma.rn.f32x2 %0, %1, %2, %0;" : "+l"(d) : "l"(a), "l"(b));
}
__device__ __forceinline__ void unpack2(unsigned long long v, float& lo, float& hi) {
    asm("mov.b64 {%0, %1}, %2;" : "=f"(lo), "=f"(hi) : "l"(v));
}
// cp.async
#define CP16(dst, src) \
    asm volatile("cp.async.cg.shared.global [%0], [%1], 16;" :: "r"(dst), "l"(src))
#define CP4(dst, src) \
    asm volatile("cp.async.ca.shared.global [%0], [%1], 4;" :: "r"(dst), "l"(src))
#define CPCOMMIT() asm volatile("cp.async.commit_group;" ::: "memory")
#define CPWAIT2()  asm volatile("cp.async.wait_group 2;" ::: "memory")
#define CPWAIT1()  asm volatile("cp.async.wait_group 1;" ::: "memory")
#define CPWAIT0()  asm volatile("cp.async.wait_group 0;" ::: "memory")

// ---------------------------------------------------------------------------
// Index dtype detection + conversion (int64 vs int32 harness layout)
// ---------------------------------------------------------------------------
__global__ void idx_detect_kernel(const unsigned int* __restrict__ v32) {
    __shared__ unsigned int s[256];
    unsigned int o = 0;
    for (int i = threadIdx.x; i < NIDX / 2; i += 256) o |= v32[2 * i + 1];
    s[threadIdx.x] = o;
    __syncthreads();
    for (int d = 128; d > 0; d >>= 1) {
        if (threadIdx.x < d) s[threadIdx.x] |= s[threadIdx.x + d];
        __syncthreads();
    }
    if (threadIdx.x == 0) g_odd_or = s[0];
}
__global__ void idx_convert_kernel(const void* __restrict__ raw) {
    int i = blockIdx.x * blockDim.x + threadIdx.x;
    if (i >= NIDX) return;
    g_rows[i] = (g_odd_or == 0u) ? (int)((const long long*)raw)[i]
                                 : ((const int*)raw)[i];
}

// ---------------------------------------------------------------------------
// Transpose + split: T = A^T (f32), plus f16 planes of X and of P1 = I+X
// ---------------------------------------------------------------------------
__global__ void transpose_cvt_kernel(const float* __restrict__ A, float* __restrict__ T,
                                     __half* __restrict__ xh, __half* __restrict__ xl,
                                     __half* __restrict__ ph, __half* __restrict__ pl) {
    __shared__ float tile[32][33];
    int x = blockIdx.x * 32 + threadIdx.x;
    int y = blockIdx.y * 32 + threadIdx.y;
#pragma unroll
    for (int j = 0; j < 32; j += 8)
        tile[threadIdx.y + j][threadIdx.x] = A[(y + j) * MSZ + x];
    __syncthreads();
    int xT = blockIdx.y * 32 + threadIdx.x;
    int yT0 = blockIdx.x * 32 + threadIdx.y;
#pragma unroll
    for (int j = 0; j < 32; j += 8) {
        int yT = yT0 + j;
        float v = tile[threadIdx.x][threadIdx.y + j];
        size_t o = (size_t)yT * MSZ + xT;
        T[o] = v;
        __half h = __float2half_rn(v);
        xh[o] = h;
        xl[o] = __float2half_rn(v - __half2float(h));
        float w = v + ((yT == xT) ? 1.0f : 0.0f);
        __half hw = __float2half_rn(w);
        ph[o] = hw;
        pl[o] = __float2half_rn(w - __half2float(hw));
    }
}

// ---------------------------------------------------------------------------
// Tensor-core f16 GEMM via mma.sync, cp.async 4-stage pipeline.
//   nseg=1: D = Ah*Bh (+C) (+I)
//   nseg=2: D = Ah*Bh + Al*Bh (+C) (+I)   [A split only]
//   nseg=3: D = Ah*Bh + Al*Bh + Ah*Bl (+C) (+I)
// ---------------------------------------------------------------------------
#define ROWB 144
#define ASTG (64 * ROWB)
#define STG  (2 * ASTG)
#define NSTAGE 4
#define GSMT (NSTAGE * STG)      // 73728

__device__ __forceinline__ void ldmx4(uint32_t* r, uint32_t addr) {
    asm volatile("ldmatrix.sync.aligned.m8n8.x4.shared.b16 {%0,%1,%2,%3}, [%4];"
                 : "=r"(r[0]), "=r"(r[1]), "=r"(r[2]), "=r"(r[3]) : "r"(addr));
}
__device__ __forceinline__ void ldmx4t(uint32_t* r, uint32_t addr) {
    asm volatile("ldmatrix.sync.aligned.m8n8.x4.trans.shared.b16 {%0,%1,%2,%3}, [%4];"
                 : "=r"(r[0]), "=r"(r[1]), "=r"(r[2]), "=r"(r[3]) : "r"(addr));
}
__device__ __forceinline__ void mma16816(float* c, const uint32_t* a,
                                         uint32_t b0, uint32_t b1) {
    asm volatile(
        "mma.sync.aligned.m16n8k16.row.col.f32.f16.f16.f32 "
        "{%0,%1,%2,%3}, {%4,%5,%6,%7}, {%8,%9}, {%0,%1,%2,%3};"
        : "+f"(c[0]), "+f"(c[1]), "+f"(c[2]), "+f"(c[3])
        : "r"(a[0]), "r"(a[1]), "r"(a[2]), "r"(a[3]), "r"(b0), "r"(b1));
}
__device__ __forceinline__ void emit_pair(__half* __restrict__ H, __half* __restrict__ L,
                                          size_t o, float2 v) {
    __half2 h = __floats2half2_rn(v.x, v.y);
    *(__half2*)&H[o] = h;
    float2 r = make_float2(v.x - __half2float(__low2half(h)),
                           v.y - __half2float(__high2half(h)));
    *(__half2*)&L[o] = __floats2half2_rn(r.x, r.y);
}

__global__ void __launch_bounds__(128) gemm_h_kernel(
    const __half* __restrict__ Ah, const __half* __restrict__ Al,
    const __half* __restrict__ Bh, const __half* __restrict__ Bl,
    const float* __restrict__ Cm, float* __restrict__ Dm, int nseg, int addI,
    __half* __restrict__ Eh, __half* __restrict__ El,
    __half* __restrict__ Fh, __half* __restrict__ Fl) {
    extern __shared__ char smem[];
    const int t = threadIdx.x;
    const int wid = t >> 5, lid = t & 31;
    const int m0 = blockIdx.y * 64, n0 = blockIdx.x * 64;
    const int wm = wid >> 1, wn = wid & 1;
    const int CMAX = nseg << 4;

    const __half* segA[3] = { Ah, Al, Ah };
    const __half* segB[3] = { Bh, Bh, Bl };

    const int lrow = (lid & 7) + ((lid >> 3) & 1) * 8;
    const int lkof = (lid >> 4) * 8;
    const int bkr  = lid & 15;
    const int bnof = (lid >> 4) * 8;
    const int lr = t >> 3, lq = t & 7;

    float acc[2][4][4];
#pragma unroll
    for (int i = 0; i < 2; i++)
#pragma unroll
        for (int j = 0; j < 4; j++)
#pragma unroll
            for (int e = 0; e < 4; e++) acc[i][j][e] = 0.0f;

    const uint32_t sbase = smem_u32(smem);

    auto load_chunk = [&](int cn, int st) {
        const __half* Ap = segA[cn >> 4];
        const __half* Bp = segB[cn >> 4];
        const int k0 = (cn & 15) * 64;
        const uint32_t sa = sbase + st * STG;
        const uint32_t sb = sa + ASTG;
#pragma unroll
        for (int i = 0; i < 4; i++) {
            int r = lr + 16 * i;
            uint32_t so = (uint32_t)(r * ROWB + lq * 16);
            CP16(sa + so, Ap + (size_t)(m0 + r) * MSZ + k0 + lq * 8);
            CP16(sb + so, Bp + (size_t)(k0 + r) * MSZ + n0 + lq * 8);
        }
        CPCOMMIT();
    };

    load_chunk(0, 0);
    load_chunk(1, 1);
    load_chunk(2, 2);

    for (int c = 0; c < CMAX; c++) {
        CPWAIT2();
        __syncthreads();

        if (c + 3 < CMAX) load_chunk(c + 3, (c + 3) & (NSTAGE - 1));
        else CPCOMMIT();

        const uint32_t sa = sbase + (c & (NSTAGE - 1)) * STG;
        const uint32_t sb = sa + ASTG;
#pragma unroll
        for (int ks = 0; ks < 4; ks++) {
            uint32_t af[2][4], bf[2][4];
#pragma unroll
            for (int i = 0; i < 2; i++)
                ldmx4(af[i], sa + (uint32_t)((wm * 32 + i * 16 + lrow) * ROWB +
                                             (ks * 16 + lkof) * 2));
#pragma unroll
            for (int j2 = 0; j2 < 2; j2++)
                ldmx4t(bf[j2], sb + (uint32_t)((ks * 16 + bkr) * ROWB +
                                               (wn * 32 + j2 * 16 + bnof) * 2));
#pragma unroll
            for (int i = 0; i < 2; i++)
#pragma unroll
                for (int j = 0; j < 4; j++)
                    mma16816(acc[i][j], af[i], bf[j >> 1][2 * (j & 1)],
                             bf[j >> 1][2 * (j & 1) + 1]);
        }
        __syncthreads();
    }

    const int g = lid >> 2, q = lid & 3;
#pragma unroll
    for (int i = 0; i < 2; i++) {
#pragma unroll
        for (int j = 0; j < 4; j++) {
            int r0 = m0 + wm * 32 + i * 16 + g;
            int r1 = r0 + 8;
            int cc = n0 + wn * 32 + j * 8 + q * 2;
            float2 v0 = make_float2(acc[i][j][0], acc[i][j][1]);
            float2 v1 = make_float2(acc[i][j][2], acc[i][j][3]);
            if (Cm) {
                float2 c0 = *(const float2*)&Cm[(size_t)r0 * MSZ + cc];
                float2 c1 = *(const float2*)&Cm[(size_t)r1 * MSZ + cc];
                v0.x += c0.x; v0.y += c0.y;
                v1.x += c1.x; v1.y += c1.y;
            }
            if (addI) {
                if (r0 == cc)     v0.x += 1.0f;
                if (r0 == cc + 1) v0.y += 1.0f;
                if (r1 == cc)     v1.x += 1.0f;
                if (r1 == cc + 1) v1.y += 1.0f;
            }
            size_t o0 = (size_t)r0 * MSZ + cc, o1 = (size_t)r1 * MSZ + cc;
            *(float2*)&Dm[o0] = v0;
            *(float2*)&Dm[o1] = v1;
            if (Eh) { emit_pair(Eh, El, o0, v0); emit_pair(Eh, El, o1, v1); }
            if (Fh) {
                float2 w0 = v0, w1 = v1;
                if (r0 == cc)     w0.x += 1.0f;
                if (r0 == cc + 1) w0.y += 1.0f;
                if (r1 == cc)     w1.x += 1.0f;
                if (r1 == cc + 1) w1.y += 1.0f;
                emit_pair(Fh, Fl, o0, w0); emit_pair(Fh, Fl, o1, w1);
            }
        }
    }
}

// ---------------------------------------------------------------------------
// Fused sigma + z, pipelined gather:
//   sigma = mu + eps*exp(logstd) (written to out, kept in smem)
//   z[b]  = S[idx[b],:][:,idx[b]] @ sigma[b]
// j-dim in 4 chunks of 32; cp.async gather of chunk c+2 overlaps compute of c.
// sub stored transposed [jj][i] (stride 130) -> LDS.64 row-pairs + fma2.
// ---------------------------------------------------------------------------
#define JC 32
#define SUBSTR 130
#define SUBB (JC * SUBSTR)                 // floats per buffer
#define ZSMEM ((NPER * DDIM + 3 * SUBB + NPER) * 4)   // 32768+49920+512 = 83200
__global__ void __launch_bounds__(256) z_kernel(
    const float* __restrict__ S,
    const float4* __restrict__ mu, const float4* __restrict__ ls,
    const float4* __restrict__ ep,
    const int* __restrict__ ridx,
    float4* __restrict__ out_sigma, float* __restrict__ z) {
    extern __shared__ float zsm[];
    float* sig_s = zsm;                        // 128*64
    float* sub0  = zsm + NPER * DDIM;          // 3 buffers of JC*SUBSTR
    int*   rows  = (int*)(sub0 + 3 * SUBB);

    const int b = blockIdx.x;
    const int t = threadIdx.x;
    const uint32_t sbase = smem_u32(zsm);

    if (t < NPER) rows[t] = ridx[b * NPER + t];
    __syncthreads();   // rows visible before gather issue

    // gather issue for chunk c into buffer bf
    const int gjj = t & 31, gi0 = (t >> 5) * 16;
    auto issue_chunk = [&](int c, int bf) {
        const int cj = rows[c * JC + gjj];
        const uint32_t dst0 = sbase + (uint32_t)(NPER * DDIM + bf * SUBB + gjj * SUBSTR) * 4;
#pragma unroll
        for (int ii = 0; ii < 16; ii++) {
            int i = gi0 + ii;
            CP4(dst0 + (uint32_t)i * 4, S + (size_t)rows[i] * MSZ + cj);
        }
        CPCOMMIT();
    };

    issue_chunk(0, 0);
    issue_chunk(1, 1);

    // sigma compute overlaps in-flight gathers
    {
        const size_t base = (size_t)b * (NPER * DDIM / 4);
        float4* ss = (float4*)sig_s;
        for (int i = t; i < NPER * DDIM / 4; i += 256) {
            float4 m = mu[base + i], l = ls[base + i], e = ep[base + i];
            float4 r;
            r.x = m.x + e.x * expf(l.x);
            r.y = m.y + e.y * expf(l.y);
            r.z = m.z + e.z * expf(l.z);
            r.w = m.w + e.w * expf(l.w);
            ss[i] = r;
            out_sigma[base + i] = r;
        }
    }
    __syncthreads();   // sig ready

    const int d4 = t & 15;
    const int ig = t >> 4;
    unsigned long long acc[4][4];   // [row-pair r2][d-component]
#pragma unroll
    for (int r2 = 0; r2 < 4; r2++)
#pragma unroll
        for (int d = 0; d < 4; d++) acc[r2][d] = 0ull;

    const float4* sig4 = (const float4*)sig_s;
    for (int c = 0; c < 4; c++) {
        if (c < 3) { CPWAIT1(); } else { CPWAIT0(); }
        __syncthreads();                       // chunk c visible; chunk c-1 compute done
        if (c + 2 < 4) issue_chunk(c + 2, (c + 2) % 3);

        const float* sb = sub0 + (c % 3) * SUBB;
#pragma unroll
        for (int jj = 0; jj < JC; jj++) {
            float4 sv = sig4[(c * JC + jj) * (DDIM / 4) + d4];
            unsigned long long sd[4];
            sd[0] = pack2(sv.x, sv.x);
            sd[1] = pack2(sv.y, sv.y);
            sd[2] = pack2(sv.z, sv.z);
            sd[3] = pack2(sv.w, sv.w);
            const float* row = sb + jj * SUBSTR + ig * 8;
#pragma unroll
            for (int r2 = 0; r2 < 4; r2++) {
                unsigned long long a2 =
                    *(const unsigned long long*)(row + 2 * r2);
#pragma unroll
                for (int d = 0; d < 4; d++)
                    fma2(acc[r2][d], a2, sd[d]);
            }
        }
    }

    float4* zp = (float4*)(z + (size_t)b * NPER * DDIM);
#pragma unroll
    for (int r2 = 0; r2 < 4; r2++) {
        float4 v0, v1;
        unpack2(acc[r2][0], v0.x, v1.x);
        unpack2(acc[r2][1], v0.y, v1.y);
        unpack2(acc[r2][2], v0.z, v1.z);
        unpack2(acc[r2][3], v0.w, v1.w);
        int row0 = ig * 8 + 2 * r2;
        zp[row0 * (DDIM / 4) + d4] = v0;
        zp[(row0 + 1) * (DDIM / 4) + d4] = v1;
    }
}

// ---------------------------------------------------------------------------
// kernel_launch — order-8 Neumann: S = (I+X)(I+X2)(I+X4) = Q1 * P4
// ---------------------------------------------------------------------------
extern "C" void kernel_launch(void* const* d_in, const int* in_sizes, int n_in,
                              void* d_out, int out_size) {
    const float* A      = (const float*)d_in[0];
    const float* mu     = (const float*)d_in[1];
    const float* logstd = (const float*)d_in[2];
    const float* eps    = (const float*)d_in[3];
    const void*  nidx   = d_in[4];

    float* out_sigma = (float*)d_out;
    float* out_z     = out_sigma + SIGN;

    float* bufs = nullptr;
    cudaGetSymbolAddress((void**)&bufs, g_scratch);
    __half* hfb = nullptr;
    cudaGetSymbolAddress((void**)&hfb, g_hf);
    int* rows_dev = nullptr;
    cudaGetSymbolAddress((void**)&rows_dev, g_rows);

    float* BX   = bufs + 0 * M2;  // X
    float* BX2  = bufs + 1 * M2;  // X2
    float* BX4  = bufs + 2 * M2;  // X4 (scratch sink)
    float* BQ1  = bufs + 5 * M2;  // Q1 -> S

    auto P = [&](int p, int hl) { return hfb + ((size_t)(p * 2 + hl)) * M2; };
    __half* NUL = nullptr;

    dim3 gT(MSZ / 32, MSZ / 32), bT(32, 8);
    dim3 gG(MSZ / 64, MSZ / 64);    // (16, 16) = 256 CTAs

    cudaFuncSetAttribute(gemm_h_kernel, cudaFuncAttributeMaxDynamicSharedMemorySize, GSMT);
    cudaFuncSetAttribute(z_kernel, cudaFuncAttributeMaxDynamicSharedMemorySize, ZSMEM);

    idx_detect_kernel<<<1, 256>>>((const unsigned int*)nidx);
    idx_convert_kernel<<<NIDX / 256, 256>>>(nidx);

#define GEMM_T(pa, pb, Cp, Dp, ns, ai, pe, pf) \
    gemm_h_kernel<<<gG, 128, GSMT>>>(P(pa,0), P(pa,1), P(pb,0), P(pb,1), Cp, Dp, ns, ai, \
        (pe) < 0 ? NUL : P(pe,0), (pe) < 0 ? NUL : P(pe,1), \
        (pf) < 0 ? NUL : P(pf,0), (pf) < 0 ? NUL : P(pf,1))

    // pairs: 0=X 1=P1 2=X2 4=P4 5=Q1
    transpose_cvt_kernel<<<gT, bT>>>(A, BX, P(0,0), P(0,1), P(1,0), P(1,1));
    GEMM_T(0, 0, (const float*)nullptr, BX2, 1, 0, 2, -1);  // X2 = X*X, emit X2
    GEMM_T(2, 2, (const float*)nullptr, BX4, 1, 0, -1, 4);  // X4 = X2*X2, emit P4=I+X4
    GEMM_T(1, 2, BX, BQ1, 1, 1, 5, -1);                     // Q1 = P1*X2 + X + I, emit Q1
    GEMM_T(5, 4, (const float*)nullptr, BQ1, 2, 0, -1, -1); // S = Q1*P4 (A-split, nseg=2)

    z_kernel<<<NBAT, 256, ZSMEM>>>(BQ1, (const float4*)mu, (const float4*)logstd,
                                   (const float4*)eps, rows_dev,
                                   (float4*)out_sigma, out_z);
#undef GEMM_T
}

// round 16
// speedup vs baseline: 1.0233x; 1.0233x over previous
#include <cuda_runtime.h>
#include <cuda_bf16.h>
#include <cuda_fp16.h>
#include <math.h>
#include <stdint.h>

#define MSZ   1024
#define M2    (MSZ * MSZ)
#define NPER  128
#define DDIM  64
#define NBAT  2048
#define NIDX  (NBAT * NPER)          // 262144
#define SIGN  (NBAT * NPER * DDIM)   // 16777216

// f32 scratch (6 x 4MB) + f16 planes (8 pairs hi/lo = 16 planes x 2MB)
__device__ float g_scratch[6 * M2];
__device__ __half g_hf[16 * M2];
__device__ int g_rows[NIDX];
__device__ unsigned int g_odd_or;

__device__ __forceinline__ uint32_t smem_u32(const void* p) {
    uint32_t a;
    asm("{ .reg .u64 t; cvta.to.shared.u64 t, %1; cvt.u32.u64 %0, t; }" : "=r"(a) : "l"(p));
    return a;
}
// f32x2 packed helpers
__device__ __forceinline__ unsigned long long pack2(float x, float y) {
    unsigned long long r;
    asm("mov.b64 %0, {%1, %2};" : "=l"(r) : "f"(x), "f"(y));
    return r;
}
__device__ __forceinline__ void fma2(unsigned long long& d,
                                     unsigned long long a, unsigned long long b) {
    asm("fma.rn.f32x2 %0, %1, %2, %0;" : "+l"(d) : "l"(a), "l"(b));
}
__device__ __forceinline__ void unpack2(unsigned long long v, float& lo, float& hi) {
    asm("mov.b64 {%0, %1}, %2;" : "=f"(lo), "=f"(hi) : "l"(v));
}
// cp.async (GEMM path)
#define CP16(dst, src) \
    asm volatile("cp.async.cg.shared.global [%0], [%1], 16;" :: "r"(dst), "l"(src))
#define CPCOMMIT() asm volatile("cp.async.commit_group;" ::: "memory")
#define CPWAIT2()  asm volatile("cp.async.wait_group 2;" ::: "memory")

// ---------------------------------------------------------------------------
// Index dtype detection + conversion (int64 vs int32 harness layout)
// ---------------------------------------------------------------------------
__global__ void idx_detect_kernel(const unsigned int* __restrict__ v32) {
    __shared__ unsigned int s[256];
    unsigned int o = 0;
    for (int i = threadIdx.x; i < NIDX / 2; i += 256) o |= v32[2 * i + 1];
    s[threadIdx.x] = o;
    __syncthreads();
    for (int d = 128; d > 0; d >>= 1) {
        if (threadIdx.x < d) s[threadIdx.x] |= s[threadIdx.x + d];
        __syncthreads();
    }
    if (threadIdx.x == 0) g_odd_or = s[0];
}
__global__ void idx_convert_kernel(const void* __restrict__ raw) {
    int i = blockIdx.x * blockDim.x + threadIdx.x;
    if (i >= NIDX) return;
    g_rows[i] = (g_odd_or == 0u) ? (int)((const long long*)raw)[i]
                                 : ((const int*)raw)[i];
}

// ---------------------------------------------------------------------------
// Transpose + split: T = A^T (f32), plus f16 planes of X and of P1 = I+X
// ---------------------------------------------------------------------------
__global__ void transpose_cvt_kernel(const float* __restrict__ A, float* __restrict__ T,
                                     __half* __restrict__ xh, __half* __restrict__ xl,
                                     __half* __restrict__ ph, __half* __restrict__ pl) {
    __shared__ float tile[32][33];
    int x = blockIdx.x * 32 + threadIdx.x;
    int y = blockIdx.y * 32 + threadIdx.y;
#pragma unroll
    for (int j = 0; j < 32; j += 8)
        tile[threadIdx.y + j][threadIdx.x] = A[(y + j) * MSZ + x];
    __syncthreads();
    int xT = blockIdx.y * 32 + threadIdx.x;
    int yT0 = blockIdx.x * 32 + threadIdx.y;
#pragma unroll
    for (int j = 0; j < 32; j += 8) {
        int yT = yT0 + j;
        float v = tile[threadIdx.x][threadIdx.y + j];
        size_t o = (size_t)yT * MSZ + xT;
        T[o] = v;
        __half h = __float2half_rn(v);
        xh[o] = h;
        xl[o] = __float2half_rn(v - __half2float(h));
        float w = v + ((yT == xT) ? 1.0f : 0.0f);
        __half hw = __float2half_rn(w);
        ph[o] = hw;
        pl[o] = __float2half_rn(w - __half2float(hw));
    }
}

// ---------------------------------------------------------------------------
// Tensor-core f16 GEMM via mma.sync, cp.async 4-stage pipeline.
//   nseg=1: D = Ah*Bh (+C) (+I)
//   nseg=2: D = Ah*Bh + Al*Bh (+C) (+I)   [A split only]
//   nseg=3: D = Ah*Bh + Al*Bh + Ah*Bl (+C) (+I)
// ---------------------------------------------------------------------------
#define ROWB 144
#define ASTG (64 * ROWB)
#define STG  (2 * ASTG)
#define NSTAGE 4
#define GSMT (NSTAGE * STG)      // 73728

__device__ __forceinline__ void ldmx4(uint32_t* r, uint32_t addr) {
    asm volatile("ldmatrix.sync.aligned.m8n8.x4.shared.b16 {%0,%1,%2,%3}, [%4];"
                 : "=r"(r[0]), "=r"(r[1]), "=r"(r[2]), "=r"(r[3]) : "r"(addr));
}
__device__ __forceinline__ void ldmx4t(uint32_t* r, uint32_t addr) {
    asm volatile("ldmatrix.sync.aligned.m8n8.x4.trans.shared.b16 {%0,%1,%2,%3}, [%4];"
                 : "=r"(r[0]), "=r"(r[1]), "=r"(r[2]), "=r"(r[3]) : "r"(addr));
}
__device__ __forceinline__ void mma16816(float* c, const uint32_t* a,
                                         uint32_t b0, uint32_t b1) {
    asm volatile(
        "mma.sync.aligned.m16n8k16.row.col.f32.f16.f16.f32 "
        "{%0,%1,%2,%3}, {%4,%5,%6,%7}, {%8,%9}, {%0,%1,%2,%3};"
        : "+f"(c[0]), "+f"(c[1]), "+f"(c[2]), "+f"(c[3])
        : "r"(a[0]), "r"(a[1]), "r"(a[2]), "r"(a[3]), "r"(b0), "r"(b1));
}
__device__ __forceinline__ void emit_pair(__half* __restrict__ H, __half* __restrict__ L,
                                          size_t o, float2 v) {
    __half2 h = __floats2half2_rn(v.x, v.y);
    *(__half2*)&H[o] = h;
    float2 r = make_float2(v.x - __half2float(__low2half(h)),
                           v.y - __half2float(__high2half(h)));
    *(__half2*)&L[o] = __floats2half2_rn(r.x, r.y);
}

__global__ void __launch_bounds__(128) gemm_h_kernel(
    const __half* __restrict__ Ah, const __half* __restrict__ Al,
    const __half* __restrict__ Bh, const __half* __restrict__ Bl,
    const float* __restrict__ Cm, float* __restrict__ Dm, int nseg, int addI,
    __half* __restrict__ Eh, __half* __restrict__ El,
    __half* __restrict__ Fh, __half* __restrict__ Fl) {
    extern __shared__ char smem[];
    const int t = threadIdx.x;
    const int wid = t >> 5, lid = t & 31;
    const int m0 = blockIdx.y * 64, n0 = blockIdx.x * 64;
    const int wm = wid >> 1, wn = wid & 1;
    const int CMAX = nseg << 4;

    const __half* segA[3] = { Ah, Al, Ah };
    const __half* segB[3] = { Bh, Bh, Bl };

    const int lrow = (lid & 7) + ((lid >> 3) & 1) * 8;
    const int lkof = (lid >> 4) * 8;
    const int bkr  = lid & 15;
    const int bnof = (lid >> 4) * 8;
    const int lr = t >> 3, lq = t & 7;

    float acc[2][4][4];
#pragma unroll
    for (int i = 0; i < 2; i++)
#pragma unroll
        for (int j = 0; j < 4; j++)
#pragma unroll
            for (int e = 0; e < 4; e++) acc[i][j][e] = 0.0f;

    const uint32_t sbase = smem_u32(smem);

    auto load_chunk = [&](int cn, int st) {
        const __half* Ap = segA[cn >> 4];
        const __half* Bp = segB[cn >> 4];
        const int k0 = (cn & 15) * 64;
        const uint32_t sa = sbase + st * STG;
        const uint32_t sb = sa + ASTG;
#pragma unroll
        for (int i = 0; i < 4; i++) {
            int r = lr + 16 * i;
            uint32_t so = (uint32_t)(r * ROWB + lq * 16);
            CP16(sa + so, Ap + (size_t)(m0 + r) * MSZ + k0 + lq * 8);
            CP16(sb + so, Bp + (size_t)(k0 + r) * MSZ + n0 + lq * 8);
        }
        CPCOMMIT();
    };

    load_chunk(0, 0);
    load_chunk(1, 1);
    load_chunk(2, 2);

    for (int c = 0; c < CMAX; c++) {
        CPWAIT2();
        __syncthreads();

        if (c + 3 < CMAX) load_chunk(c + 3, (c + 3) & (NSTAGE - 1));
        else CPCOMMIT();

        const uint32_t sa = sbase + (c & (NSTAGE - 1)) * STG;
        const uint32_t sb = sa + ASTG;
#pragma unroll
        for (int ks = 0; ks < 4; ks++) {
            uint32_t af[2][4], bf[2][4];
#pragma unroll
            for (int i = 0; i < 2; i++)
                ldmx4(af[i], sa + (uint32_t)((wm * 32 + i * 16 + lrow) * ROWB +
                                             (ks * 16 + lkof) * 2));
#pragma unroll
            for (int j2 = 0; j2 < 2; j2++)
                ldmx4t(bf[j2], sb + (uint32_t)((ks * 16 + bkr) * ROWB +
                                               (wn * 32 + j2 * 16 + bnof) * 2));
#pragma unroll
            for (int i = 0; i < 2; i++)
#pragma unroll
                for (int j = 0; j < 4; j++)
                    mma16816(acc[i][j], af[i], bf[j >> 1][2 * (j & 1)],
                             bf[j >> 1][2 * (j & 1) + 1]);
        }
        __syncthreads();
    }

    const int g = lid >> 2, q = lid & 3;
#pragma unroll
    for (int i = 0; i < 2; i++) {
#pragma unroll
        for (int j = 0; j < 4; j++) {
            int r0 = m0 + wm * 32 + i * 16 + g;
            int r1 = r0 + 8;
            int cc = n0 + wn * 32 + j * 8 + q * 2;
            float2 v0 = make_float2(acc[i][j][0], acc[i][j][1]);
            float2 v1 = make_float2(acc[i][j][2], acc[i][j][3]);
            if (Cm) {
                float2 c0 = *(const float2*)&Cm[(size_t)r0 * MSZ + cc];
                float2 c1 = *(const float2*)&Cm[(size_t)r1 * MSZ + cc];
                v0.x += c0.x; v0.y += c0.y;
                v1.x += c1.x; v1.y += c1.y;
            }
            if (addI) {
                if (r0 == cc)     v0.x += 1.0f;
                if (r0 == cc + 1) v0.y += 1.0f;
                if (r1 == cc)     v1.x += 1.0f;
                if (r1 == cc + 1) v1.y += 1.0f;
            }
            size_t o0 = (size_t)r0 * MSZ + cc, o1 = (size_t)r1 * MSZ + cc;
            *(float2*)&Dm[o0] = v0;
            *(float2*)&Dm[o1] = v1;
            if (Eh) { emit_pair(Eh, El, o0, v0); emit_pair(Eh, El, o1, v1); }
            if (Fh) {
                float2 w0 = v0, w1 = v1;
                if (r0 == cc)     w0.x += 1.0f;
                if (r0 == cc + 1) w0.y += 1.0f;
                if (r1 == cc)     w1.x += 1.0f;
                if (r1 == cc + 1) w1.y += 1.0f;
                emit_pair(Fh, Fl, o0, w0); emit_pair(Fh, Fl, o1, w1);
            }
        }
    }
}

// ---------------------------------------------------------------------------
// Fused sigma + z with register-double-buffered gather:
//   sigma = mu + eps*exp(logstd) (written to out, kept in smem)
//   z[b]  = S[idx[b],:][:,idx[b]] @ sigma[b]
// j split in 2 chunks of 64. LDG chunk0 -> sigma compute (hides latency)
// -> STS0 -> sync -> LDG chunk1 -> compute chunk0 (hides latency) -> STS1
// -> sync -> compute chunk1. Same accumulation order as the serial version.
// ---------------------------------------------------------------------------
#define ZSMEM ((NPER * NPER + NPER * DDIM + NPER) * 4)
__global__ void __launch_bounds__(256) z_kernel(
    const float* __restrict__ S,
    const float4* __restrict__ mu, const float4* __restrict__ ls,
    const float4* __restrict__ ep,
    const int* __restrict__ ridx,
    float4* __restrict__ out_sigma, float* __restrict__ z) {
    extern __shared__ float zsm[];
    float* sub_s = zsm;                        // 128*128
    float* sig_s = zsm + NPER * NPER;          // 128*64
    int*   rows  = (int*)(sig_s + NPER * DDIM);

    const int b = blockIdx.x;
    const int t = threadIdx.x;

    if (t < NPER) rows[t] = ridx[b * NPER + t];
    __syncthreads();   // rows visible to all before gather addressing

    const int tj  = t & 63;          // j within chunk
    const int ti0 = (t >> 6) * 32;   // 32 rows per thread

    // ---- issue chunk-0 gather into registers ----
    float v0[32];
    {
        const int cj = rows[tj];
#pragma unroll
        for (int u = 0; u < 32; u++)
            v0[u] = S[(size_t)rows[ti0 + u] * MSZ + cj];
    }

    // ---- sigma compute (overlaps chunk-0 LDG latency) ----
    {
        const size_t base = (size_t)b * (NPER * DDIM / 4);
        float4* ss = (float4*)sig_s;
        for (int i = t; i < NPER * DDIM / 4; i += 256) {
            float4 m = mu[base + i], l = ls[base + i], e = ep[base + i];
            float4 r;
            r.x = m.x + e.x * expf(l.x);
            r.y = m.y + e.y * expf(l.y);
            r.z = m.z + e.z * expf(l.z);
            r.w = m.w + e.w * expf(l.w);
            ss[i] = r;
            out_sigma[base + i] = r;
        }
    }

    // ---- STS chunk 0 (column writes, conflict-free) ----
#pragma unroll
    for (int u = 0; u < 32; u++)
        sub_s[(ti0 + u) * NPER + tj] = v0[u];
    __syncthreads();

    // ---- issue chunk-1 gather (latency hidden by compute chunk 0) ----
    float v1[32];
    {
        const int cj = rows[64 + tj];
#pragma unroll
        for (int u = 0; u < 32; u++)
            v1[u] = S[(size_t)rows[ti0 + u] * MSZ + cj];
    }

    const int d4 = t & 15;
    const int ig = t >> 4;
    unsigned long long accA[8], accB[8];
#pragma unroll
    for (int r = 0; r < 8; r++) { accA[r] = 0ull; accB[r] = 0ull; }

    const float4* sig4 = (const float4*)sig_s;

    // ---- compute chunk 0 (j = 0..63) ----
    for (int j = 0; j < 64; j++) {
        float4 sv = sig4[j * (DDIM / 4) + d4];
        unsigned long long sxy = pack2(sv.x, sv.y);
        unsigned long long szw = pack2(sv.z, sv.w);
#pragma unroll
        for (int r = 0; r < 8; r++) {
            float a = sub_s[(ig * 8 + r) * NPER + j];
            unsigned long long aa = pack2(a, a);
            fma2(accA[r], aa, sxy);
            fma2(accB[r], aa, szw);
        }
    }

    // ---- STS chunk 1, sync ----
#pragma unroll
    for (int u = 0; u < 32; u++)
        sub_s[(ti0 + u) * NPER + 64 + tj] = v1[u];
    __syncthreads();

    // ---- compute chunk 1 (j = 64..127) ----
    for (int j = 64; j < 128; j++) {
        float4 sv = sig4[j * (DDIM / 4) + d4];
        unsigned long long sxy = pack2(sv.x, sv.y);
        unsigned long long szw = pack2(sv.z, sv.w);
#pragma unroll
        for (int r = 0; r < 8; r++) {
            float a = sub_s[(ig * 8 + r) * NPER + j];
            unsigned long long aa = pack2(a, a);
            fma2(accA[r], aa, sxy);
            fma2(accB[r], aa, szw);
        }
    }

    float4* zp = (float4*)(z + (size_t)b * NPER * DDIM);
#pragma unroll
    for (int r = 0; r < 8; r++) {
        float4 v;
        unpack2(accA[r], v.x, v.y);
        unpack2(accB[r], v.z, v.w);
        zp[(ig * 8 + r) * (DDIM / 4) + d4] = v;
    }
}

// ---------------------------------------------------------------------------
// kernel_launch — order-8 Neumann: S = (I+X)(I+X2)(I+X4) = Q1 * P4
// ---------------------------------------------------------------------------
extern "C" void kernel_launch(void* const* d_in, const int* in_sizes, int n_in,
                              void* d_out, int out_size) {
    const float* A      = (const float*)d_in[0];
    const float* mu     = (const float*)d_in[1];
    const float* logstd = (const float*)d_in[2];
    const float* eps    = (const float*)d_in[3];
    const void*  nidx   = d_in[4];

    float* out_sigma = (float*)d_out;
    float* out_z     = out_sigma + SIGN;

    float* bufs = nullptr;
    cudaGetSymbolAddress((void**)&bufs, g_scratch);
    __half* hfb = nullptr;
    cudaGetSymbolAddress((void**)&hfb, g_hf);
    int* rows_dev = nullptr;
    cudaGetSymbolAddress((void**)&rows_dev, g_rows);

    float* BX   = bufs + 0 * M2;  // X
    float* BX2  = bufs + 1 * M2;  // X2
    float* BX4  = bufs + 2 * M2;  // X4 (scratch sink)
    float* BQ1  = bufs + 5 * M2;  // Q1 -> S

    auto P = [&](int p, int hl) { return hfb + ((size_t)(p * 2 + hl)) * M2; };
    __half* NUL = nullptr;

    dim3 gT(MSZ / 32, MSZ / 32), bT(32, 8);
    dim3 gG(MSZ / 64, MSZ / 64);    // (16, 16) = 256 CTAs

    cudaFuncSetAttribute(gemm_h_kernel, cudaFuncAttributeMaxDynamicSharedMemorySize, GSMT);
    cudaFuncSetAttribute(z_kernel, cudaFuncAttributeMaxDynamicSharedMemorySize, ZSMEM);

    idx_detect_kernel<<<1, 256>>>((const unsigned int*)nidx);
    idx_convert_kernel<<<NIDX / 256, 256>>>(nidx);

#define GEMM_T(pa, pb, Cp, Dp, ns, ai, pe, pf) \
    gemm_h_kernel<<<gG, 128, GSMT>>>(P(pa,0), P(pa,1), P(pb,0), P(pb,1), Cp, Dp, ns, ai, \
        (pe) < 0 ? NUL : P(pe,0), (pe) < 0 ? NUL : P(pe,1), \
        (pf) < 0 ? NUL : P(pf,0), (pf) < 0 ? NUL : P(pf,1))

    // pairs: 0=X 1=P1 2=X2 4=P4 5=Q1
    transpose_cvt_kernel<<<gT, bT>>>(A, BX, P(0,0), P(0,1), P(1,0), P(1,1));
    GEMM_T(0, 0, (const float*)nullptr, BX2, 1, 0, 2, -1);  // X2 = X*X, emit X2
    GEMM_T(2, 2, (const float*)nullptr, BX4, 1, 0, -1, 4);  // X4 = X2*X2, emit P4=I+X4
    GEMM_T(1, 2, BX, BQ1, 1, 1, 5, -1);                     // Q1 = P1*X2 + X + I, emit Q1
    GEMM_T(5, 4, (const float*)nullptr, BQ1, 2, 0, -1, -1); // S = Q1*P4 (A-split, nseg=2)

    z_kernel<<<NBAT, 256, ZSMEM>>>(BQ1, (const float4*)mu, (const float4*)logstd,
                                   (const float4*)eps, rows_dev,
                                   (float4*)out_sigma, out_z);
#undef GEMM_T
}